// round 2
// baseline (speedup 1.0000x reference)
#include <cuda_runtime.h>
#include <cstdint>

#define Hh 192
#define Ww 192
#define HW 36864
#define NPIX 147456
#define INC 256
#define HID 16
#define MIDC 288
#define OUTC 128
#define PSTRIDE 152   // padded per-pixel stride (floats) for o1s/o3s smem

// Scratch (device globals: allocation-free per harness rules)
__device__ float g_h[2][NPIX][HID];      // (branch, pixel, channel)  ~18.9 MB
__device__ float g_mid[NPIX][MIDC];      // concat of both branch outputs ~162 MB

// group -> spatial offset (unit steps; multiplied by shift). g==8 is center (+h).
__constant__ int c_oy[9] = {-1,-1,-1, 0, 1, 1, 1, 0, 0};
__constant__ int c_ox[9] = {-1, 0, 1, 1, 1, 0,-1,-1, 0};

// ---------------------------------------------------------------------------
// Kernel 1a: 1x1 input projection (branch 0): h0 = W0 * cen + b0
// ---------------------------------------------------------------------------
__global__ void __launch_bounds__(256) k_proj1x1(const float* __restrict__ cen,
                                                 const float* __restrict__ w0,
                                                 const float* __restrict__ b0) {
    __shared__ float ws[INC][HID];            // ws[c][o] = w0[o, c]
    for (int t = threadIdx.x; t < INC * HID; t += 256) {
        int c = t >> 4, o = t & 15;
        ws[c][o] = __ldg(w0 + o * INC + c);
    }
    __syncthreads();

    int p = blockIdx.x * 256 + threadIdx.x;   // 576 blocks * 256 == NPIX exactly
    int b = p / HW, r = p - b * HW;

    float acc[HID];
#pragma unroll
    for (int o = 0; o < HID; o++) acc[o] = __ldg(b0 + o);

    const float* cp = cen + (size_t)b * INC * HW + r;
#pragma unroll 4
    for (int c = 0; c < INC; c++) {
        float v = __ldg(cp + (size_t)c * HW);
        const float4* w4 = (const float4*)ws[c];
#pragma unroll
        for (int j = 0; j < 4; j++) {
            float4 w = w4[j];
            acc[4*j+0] = fmaf(w.x, v, acc[4*j+0]);
            acc[4*j+1] = fmaf(w.y, v, acc[4*j+1]);
            acc[4*j+2] = fmaf(w.z, v, acc[4*j+2]);
            acc[4*j+3] = fmaf(w.w, v, acc[4*j+3]);
        }
    }
    float4* hp = (float4*)g_h[0][p];
#pragma unroll
    for (int j = 0; j < 4; j++)
        hp[j] = make_float4(acc[4*j], acc[4*j+1], acc[4*j+2], acc[4*j+3]);
}

// ---------------------------------------------------------------------------
// Kernel 1b: 3x3 SAME input projection (branch 1): h1 = conv3x3(cen, W1) + b1
// Block: 256 threads = 64x4 pixel tile. Channels staged in chunks of 16.
// ---------------------------------------------------------------------------
#define CH 16
__global__ void __launch_bounds__(256) k_proj3x3(const float* __restrict__ cen,
                                                 const float* __restrict__ w1,
                                                 const float* __restrict__ b1) {
    __shared__ float tile[CH][6][66];          // (4+2) x (64+2) halo tile per channel
    __shared__ float ws[CH][9][HID];           // ws[cc][tap][o]

    int tx = threadIdx.x & 63, ty = threadIdx.x >> 6;
    int x0 = blockIdx.x * 64, y0 = blockIdx.y * 4, b = blockIdx.z;

    float acc[HID];
#pragma unroll
    for (int o = 0; o < HID; o++) acc[o] = __ldg(b1 + o);

    for (int c0 = 0; c0 < INC; c0 += CH) {
        __syncthreads();  // protect smem from previous chunk's compute
        // load input halo tile for CH channels
        for (int t = threadIdx.x; t < CH * 6 * 66; t += 256) {
            int cc = t / 396; int rem = t - cc * 396;
            int rr = rem / 66; int col = rem - rr * 66;
            int y = y0 - 1 + rr, x = x0 - 1 + col;
            float v = 0.f;
            if ((unsigned)y < Hh && (unsigned)x < Ww)
                v = __ldg(cen + (size_t)(b * INC + c0 + cc) * HW + y * Ww + x);
            tile[cc][rr][col] = v;
        }
        // load weight chunk: w1 is (HID, INC, 3, 3)
        for (int t = threadIdx.x; t < CH * 9 * HID; t += 256) {
            int cc = t / 144; int rem = t - cc * 144;
            int k9 = rem >> 4; int o = rem & 15;
            ws[cc][k9][o] = __ldg(w1 + (size_t)(o * INC + c0 + cc) * 9 + k9);
        }
        __syncthreads();

#pragma unroll 2
        for (int cc = 0; cc < CH; cc++) {
            float r[9];
#pragma unroll
            for (int dy = 0; dy < 3; dy++)
#pragma unroll
                for (int dx = 0; dx < 3; dx++)
                    r[dy*3+dx] = tile[cc][ty + dy][tx + dx];
#pragma unroll
            for (int k = 0; k < 9; k++) {
                const float4* w4 = (const float4*)ws[cc][k];
#pragma unroll
                for (int j = 0; j < 4; j++) {
                    float4 w = w4[j];
                    acc[4*j+0] = fmaf(w.x, r[k], acc[4*j+0]);
                    acc[4*j+1] = fmaf(w.y, r[k], acc[4*j+1]);
                    acc[4*j+2] = fmaf(w.z, r[k], acc[4*j+2]);
                    acc[4*j+3] = fmaf(w.w, r[k], acc[4*j+3]);
                }
            }
        }
    }

    int p = b * HW + (y0 + ty) * Ww + (x0 + tx);
    float4* hp = (float4*)g_h[1][p];
#pragma unroll
    for (int j = 0; j < 4; j++)
        hp[j] = make_float4(acc[4*j], acc[4*j+1], acc[4*j+2], acc[4*j+3]);
}

// ---------------------------------------------------------------------------
// Kernel 2: per-pixel group attention for one branch.
// Block: 288 threads = 32 pixels x 9 groups. Thread (pixel, g):
//   v = sign * h(pos + offset_g)   (zero outside image)
//   o1 = W1[g] v ; o3 = W3[g] v  -> smem ; o2 = W2[g] v -> regs
//   logits[g][q] = sc * o2 . o1s[q] ; softmax over q ; out = sum_q a_q * o3s[q]
// ---------------------------------------------------------------------------
__global__ void __launch_bounds__(288) k_attn(const float* __restrict__ w1,
                                              const float* __restrict__ w2,
                                              const float* __restrict__ w3,
                                              const float* __restrict__ scl,
                                              int br, int shift) {
    extern __shared__ float sm[];
    float* W1s = sm;                 // [9][16(c)][16(d)]  (transposed for float4 over d)
    float* W2s = sm + 2304;
    float* W3s = sm + 4608;
    float* o1s = sm + 6912;          // [32][PSTRIDE]
    float* o3s = o1s + 32 * PSTRIDE;

    for (int t = threadIdx.x; t < 2304; t += 288) {
        int g = t >> 8; int rem = t & 255; int c = rem >> 4; int d = rem & 15;
        int src = (g * 16 + d) * 16 + c;       // weights are (9, d, c)
        W1s[t] = __ldg(w1 + src);
        W2s[t] = __ldg(w2 + src);
        W3s[t] = __ldg(w3 + src);
    }
    __syncthreads();

    int pl = threadIdx.x / 9;
    int g  = threadIdx.x - pl * 9;
    int p  = blockIdx.x * 32 + pl;             // 4608 blocks * 32 == NPIX
    int b = p / HW, r = p - b * HW, y = r / Ww, x = r - y * Ww;

    int yy = y + c_oy[g] * shift, xx = x + c_ox[g] * shift;
    bool valid = ((unsigned)yy < Hh) && ((unsigned)xx < Ww);
    float sign = (g == 8) ? 1.f : -1.f;
    int sidx = valid ? (b * HW + yy * Ww + xx) : 0;

    float v[16];
    const float4* hp = (const float4*)g_h[br][sidx];
#pragma unroll
    for (int j = 0; j < 4; j++) {
        float4 t = hp[j];
        if (!valid) t = make_float4(0.f, 0.f, 0.f, 0.f);
        v[4*j+0] = sign * t.x; v[4*j+1] = sign * t.y;
        v[4*j+2] = sign * t.z; v[4*j+3] = sign * t.w;
    }

    float o[16];
    // ---- o1 -> smem
#pragma unroll
    for (int j = 0; j < 16; j++) o[j] = 0.f;
    {
        const float* Wg = W1s + g * 256;
#pragma unroll
        for (int c = 0; c < 16; c++) {
            float vc = v[c];
            const float4* w4 = (const float4*)(Wg + c * 16);
#pragma unroll
            for (int j = 0; j < 4; j++) {
                float4 w = w4[j];
                o[4*j+0] = fmaf(w.x, vc, o[4*j+0]);
                o[4*j+1] = fmaf(w.y, vc, o[4*j+1]);
                o[4*j+2] = fmaf(w.z, vc, o[4*j+2]);
                o[4*j+3] = fmaf(w.w, vc, o[4*j+3]);
            }
        }
    }
    {
        float4* dst = (float4*)(o1s + pl * PSTRIDE + g * 16);
#pragma unroll
        for (int j = 0; j < 4; j++)
            dst[j] = make_float4(o[4*j], o[4*j+1], o[4*j+2], o[4*j+3]);
    }
    // ---- o3 -> smem
#pragma unroll
    for (int j = 0; j < 16; j++) o[j] = 0.f;
    {
        const float* Wg = W3s + g * 256;
#pragma unroll
        for (int c = 0; c < 16; c++) {
            float vc = v[c];
            const float4* w4 = (const float4*)(Wg + c * 16);
#pragma unroll
            for (int j = 0; j < 4; j++) {
                float4 w = w4[j];
                o[4*j+0] = fmaf(w.x, vc, o[4*j+0]);
                o[4*j+1] = fmaf(w.y, vc, o[4*j+1]);
                o[4*j+2] = fmaf(w.z, vc, o[4*j+2]);
                o[4*j+3] = fmaf(w.w, vc, o[4*j+3]);
            }
        }
    }
    {
        float4* dst = (float4*)(o3s + pl * PSTRIDE + g * 16);
#pragma unroll
        for (int j = 0; j < 4; j++)
            dst[j] = make_float4(o[4*j], o[4*j+1], o[4*j+2], o[4*j+3]);
    }
    // ---- o2 stays in regs
#pragma unroll
    for (int j = 0; j < 16; j++) o[j] = 0.f;
    {
        const float* Wg = W2s + g * 256;
#pragma unroll
        for (int c = 0; c < 16; c++) {
            float vc = v[c];
            const float4* w4 = (const float4*)(Wg + c * 16);
#pragma unroll
            for (int j = 0; j < 4; j++) {
                float4 w = w4[j];
                o[4*j+0] = fmaf(w.x, vc, o[4*j+0]);
                o[4*j+1] = fmaf(w.y, vc, o[4*j+1]);
                o[4*j+2] = fmaf(w.z, vc, o[4*j+2]);
                o[4*j+3] = fmaf(w.w, vc, o[4*j+3]);
            }
        }
    }
    __syncthreads();

    float sc = __ldg(scl + br);
    float l[9];
    const float* basep = o1s + pl * PSTRIDE;
#pragma unroll
    for (int q = 0; q < 9; q++) {
        const float4* oq = (const float4*)(basep + q * 16);
        float s = 0.f;
#pragma unroll
        for (int j = 0; j < 4; j++) {
            float4 t = oq[j];
            s = fmaf(o[4*j+0], t.x, s);
            s = fmaf(o[4*j+1], t.y, s);
            s = fmaf(o[4*j+2], t.z, s);
            s = fmaf(o[4*j+3], t.w, s);
        }
        l[q] = s * sc;
    }
    float m = l[0];
#pragma unroll
    for (int q = 1; q < 9; q++) m = fmaxf(m, l[q]);
    float ssum = 0.f;
#pragma unroll
    for (int q = 0; q < 9; q++) { l[q] = __expf(l[q] - m); ssum += l[q]; }
    float inv = 1.f / ssum;

    float outv[16];
#pragma unroll
    for (int j = 0; j < 16; j++) outv[j] = 0.f;
    const float* b3 = o3s + pl * PSTRIDE;
#pragma unroll
    for (int q = 0; q < 9; q++) {
        float a = l[q] * inv;
        const float4* oq = (const float4*)(b3 + q * 16);
#pragma unroll
        for (int j = 0; j < 4; j++) {
            float4 t = oq[j];
            outv[4*j+0] = fmaf(a, t.x, outv[4*j+0]);
            outv[4*j+1] = fmaf(a, t.y, outv[4*j+1]);
            outv[4*j+2] = fmaf(a, t.z, outv[4*j+2]);
            outv[4*j+3] = fmaf(a, t.w, outv[4*j+3]);
        }
    }
    float4* mp = (float4*)(g_mid[p] + br * 144 + g * 16);
#pragma unroll
    for (int j = 0; j < 4; j++)
        mp[j] = make_float4(outv[4*j], outv[4*j+1], outv[4*j+2], outv[4*j+3]);
}

// ---------------------------------------------------------------------------
// Kernel 3: final 1x1 conv (288 -> 128) + bias. Thread = 1 pixel, 4 passes
// of 32 output channels. Weight in smem transposed [i][o] (uniform broadcast).
// ---------------------------------------------------------------------------
__global__ void __launch_bounds__(512) k_out(const float* __restrict__ ow,
                                             const float* __restrict__ ob,
                                             float* __restrict__ out) {
    extern __shared__ float ws[];              // [288][128], 147456 B
    for (int t = threadIdx.x; t < MIDC * OUTC; t += 512) {
        int i = t >> 7, o = t & 127;
        ws[t] = __ldg(ow + o * MIDC + i);
    }
    __syncthreads();

    int p = blockIdx.x * 512 + threadIdx.x;    // 288 blocks * 512 == NPIX
    int b = p / HW, r = p - b * HW;
    const float4* mp = (const float4*)g_mid[p];
    float* op = out + (size_t)b * OUTC * HW + r;

#pragma unroll
    for (int pass = 0; pass < 4; pass++) {
        float acc[32];
#pragma unroll
        for (int j = 0; j < 32; j++) acc[j] = __ldg(ob + pass * 32 + j);

#pragma unroll 2
        for (int i4 = 0; i4 < MIDC / 4; i4++) {
            float4 mv = mp[i4];
            float mvals[4] = {mv.x, mv.y, mv.z, mv.w};
#pragma unroll
            for (int s = 0; s < 4; s++) {
                int i = i4 * 4 + s;
                const float4* w4 = (const float4*)(ws + i * OUTC + pass * 32);
                float mm = mvals[s];
#pragma unroll
                for (int j = 0; j < 8; j++) {
                    float4 w = w4[j];
                    acc[4*j+0] = fmaf(w.x, mm, acc[4*j+0]);
                    acc[4*j+1] = fmaf(w.y, mm, acc[4*j+1]);
                    acc[4*j+2] = fmaf(w.z, mm, acc[4*j+2]);
                    acc[4*j+3] = fmaf(w.w, mm, acc[4*j+3]);
                }
            }
        }
#pragma unroll
        for (int j = 0; j < 32; j++)
            op[(size_t)(pass * 32 + j) * HW] = acc[j];
    }
}

// ---------------------------------------------------------------------------
extern "C" void kernel_launch(void* const* d_in, const int* in_sizes, int n_in,
                              void* d_out, int out_size) {
    const float* cen   = (const float*)d_in[0];
    const float* in_w0 = (const float*)d_in[1];
    const float* in_b0 = (const float*)d_in[2];
    const float* in_w1 = (const float*)d_in[3];
    const float* in_b1 = (const float*)d_in[4];
    const float* w1_0  = (const float*)d_in[5];
    const float* w2_0  = (const float*)d_in[6];
    const float* w3_0  = (const float*)d_in[7];
    const float* w1_1  = (const float*)d_in[8];
    const float* w2_1  = (const float*)d_in[9];
    const float* w3_1  = (const float*)d_in[10];
    const float* scale = (const float*)d_in[11];
    const float* out_w = (const float*)d_in[12];
    const float* out_b = (const float*)d_in[13];
    float* out = (float*)d_out;

    const int attnSmem = (6912 + 2 * 32 * PSTRIDE) * (int)sizeof(float);  // 66560 B
    const int outSmem  = MIDC * OUTC * (int)sizeof(float);                // 147456 B
    cudaFuncSetAttribute(k_attn, cudaFuncAttributeMaxDynamicSharedMemorySize, attnSmem);
    cudaFuncSetAttribute(k_out,  cudaFuncAttributeMaxDynamicSharedMemorySize, outSmem);

    k_proj1x1<<<NPIX / 256, 256>>>(cen, in_w0, in_b0);
    k_proj3x3<<<dim3(Ww / 64, Hh / 4, 4), 256>>>(cen, in_w1, in_b1);
    k_attn<<<NPIX / 32, 288, attnSmem>>>(w1_0, w2_0, w3_0, scale, 0, 1);
    k_attn<<<NPIX / 32, 288, attnSmem>>>(w1_1, w2_1, w3_1, scale, 1, 5);
    k_out<<<NPIX / 512, 512, outSmem>>>(out_w, out_b, out);
}

// round 6
// speedup vs baseline: 2.0414x; 2.0414x over previous
#include <cuda_runtime.h>
#include <cstdint>

#define Hh 192
#define Ww 192
#define HW 36864
#define NPIX 147456
#define INC 256
#define HID 16
#define MIDC 288
#define OUTC 128
#define XS 33            // exchange stride (floats) for o1s/o3s: conflict-free
#define WSTR 132         // k_out weight smem row stride (floats); 16B-aligned, low-conflict

// Scratch (device globals: allocation-free per harness rules)
__device__ float4 g_h4[2][4][NPIX];      // (branch, ch-chunk, pixel) plane-major ~18.9 MB
__device__ float  g_mid[MIDC][NPIX];     // channel-major concat of both branches ~162 MB

// group -> spatial offset (unit steps; multiplied by shift). g==8 is center (+h).
__constant__ int c_oy[9] = {-1,-1,-1, 0, 1, 1, 1, 0, 0};
__constant__ int c_ox[9] = {-1, 0, 1, 1, 1, 0,-1,-1, 0};

// ---------------------------------------------------------------------------
// Kernel 1a: 1x1 input projection (branch 0): h0 = W0 * cen + b0
// ---------------------------------------------------------------------------
__global__ void __launch_bounds__(256) k_proj1x1(const float* __restrict__ cen,
                                                 const float* __restrict__ w0,
                                                 const float* __restrict__ b0) {
    __shared__ float ws[INC][HID];            // ws[c][o] = w0[o, c]
    for (int t = threadIdx.x; t < INC * HID; t += 256) {
        int c = t >> 4, o = t & 15;
        ws[c][o] = __ldg(w0 + o * INC + c);
    }
    __syncthreads();

    int p = blockIdx.x * 256 + threadIdx.x;   // 576 blocks * 256 == NPIX exactly
    int b = p / HW, r = p - b * HW;

    float acc[HID];
#pragma unroll
    for (int o = 0; o < HID; o++) acc[o] = __ldg(b0 + o);

    const float* cp = cen + (size_t)b * INC * HW + r;
#pragma unroll 4
    for (int c = 0; c < INC; c++) {
        float v = __ldg(cp + (size_t)c * HW);
        const float4* w4 = (const float4*)ws[c];
#pragma unroll
        for (int j = 0; j < 4; j++) {
            float4 w = w4[j];
            acc[4*j+0] = fmaf(w.x, v, acc[4*j+0]);
            acc[4*j+1] = fmaf(w.y, v, acc[4*j+1]);
            acc[4*j+2] = fmaf(w.z, v, acc[4*j+2]);
            acc[4*j+3] = fmaf(w.w, v, acc[4*j+3]);
        }
    }
#pragma unroll
    for (int j = 0; j < 4; j++)
        g_h4[0][j][p] = make_float4(acc[4*j], acc[4*j+1], acc[4*j+2], acc[4*j+3]);
}

// ---------------------------------------------------------------------------
// Kernel 1b: 3x3 SAME input projection (branch 1): h1 = conv3x3(cen, W1) + b1
// Block: 256 threads = 64x4 pixel tile. Channels staged in chunks of 16.
// ---------------------------------------------------------------------------
#define CH 16
__global__ void __launch_bounds__(256) k_proj3x3(const float* __restrict__ cen,
                                                 const float* __restrict__ w1,
                                                 const float* __restrict__ b1) {
    __shared__ float tile[CH][6][66];          // (4+2) x (64+2) halo tile per channel
    __shared__ float ws[CH][9][HID];           // ws[cc][tap][o]

    int tx = threadIdx.x & 63, ty = threadIdx.x >> 6;
    int x0 = blockIdx.x * 64, y0 = blockIdx.y * 4, b = blockIdx.z;

    float acc[HID];
#pragma unroll
    for (int o = 0; o < HID; o++) acc[o] = __ldg(b1 + o);

    for (int c0 = 0; c0 < INC; c0 += CH) {
        __syncthreads();  // protect smem from previous chunk's compute
        // load input halo tile for CH channels
        for (int t = threadIdx.x; t < CH * 6 * 66; t += 256) {
            int cc = t / 396; int rem = t - cc * 396;
            int rr = rem / 66; int col = rem - rr * 66;
            int y = y0 - 1 + rr, x = x0 - 1 + col;
            float v = 0.f;
            if ((unsigned)y < Hh && (unsigned)x < Ww)
                v = __ldg(cen + (size_t)(b * INC + c0 + cc) * HW + y * Ww + x);
            tile[cc][rr][col] = v;
        }
        // load weight chunk: w1 is (HID, INC, 3, 3)
        for (int t = threadIdx.x; t < CH * 9 * HID; t += 256) {
            int cc = t / 144; int rem = t - cc * 144;
            int k9 = rem >> 4; int o = rem & 15;
            ws[cc][k9][o] = __ldg(w1 + (size_t)(o * INC + c0 + cc) * 9 + k9);
        }
        __syncthreads();

#pragma unroll 2
        for (int cc = 0; cc < CH; cc++) {
            float r[9];
#pragma unroll
            for (int dy = 0; dy < 3; dy++)
#pragma unroll
                for (int dx = 0; dx < 3; dx++)
                    r[dy*3+dx] = tile[cc][ty + dy][tx + dx];
#pragma unroll
            for (int k = 0; k < 9; k++) {
                const float4* w4 = (const float4*)ws[cc][k];
#pragma unroll
                for (int j = 0; j < 4; j++) {
                    float4 w = w4[j];
                    acc[4*j+0] = fmaf(w.x, r[k], acc[4*j+0]);
                    acc[4*j+1] = fmaf(w.y, r[k], acc[4*j+1]);
                    acc[4*j+2] = fmaf(w.z, r[k], acc[4*j+2]);
                    acc[4*j+3] = fmaf(w.w, r[k], acc[4*j+3]);
                }
            }
        }
    }

    int p = b * HW + (y0 + ty) * Ww + (x0 + tx);
#pragma unroll
    for (int j = 0; j < 4; j++)
        g_h4[1][j][p] = make_float4(acc[4*j], acc[4*j+1], acc[4*j+2], acc[4*j+3]);
}

// ---------------------------------------------------------------------------
// Kernel 2: per-pixel group attention for one branch.
// Block: 288 threads = 9 warps; warp = group g, lane = pixel.
//  - weight LDS are warp-uniform broadcasts (conflict-free)
//  - g_h gathers are 32-consecutive-pixel coalesced
//  - o1/o3 exchange via smem layout [(g*16+d)*XS + lane]: scalar, conflict-free
// ---------------------------------------------------------------------------
__global__ void __launch_bounds__(288) k_attn(const float* __restrict__ w1,
                                              const float* __restrict__ w2,
                                              const float* __restrict__ w3,
                                              const float* __restrict__ scl,
                                              int br, int shift) {
    extern __shared__ float sm[];
    float* W1s = sm;                 // [9][16(c)][16(d)]
    float* W2s = sm + 2304;
    float* W3s = sm + 4608;
    float* o1s = sm + 6912;          // [144][XS]
    float* o3s = o1s + 144 * XS;

    for (int t = threadIdx.x; t < 2304; t += 288) {
        int g = t >> 8; int rem = t & 255; int c = rem >> 4; int d = rem & 15;
        int src = (g * 16 + d) * 16 + c;       // weights are (9, d, c)
        W1s[t] = __ldg(w1 + src);
        W2s[t] = __ldg(w2 + src);
        W3s[t] = __ldg(w3 + src);
    }
    __syncthreads();

    int g  = threadIdx.x >> 5;                 // warp id == group (0..8)
    int pl = threadIdx.x & 31;                 // lane == pixel within block
    int p  = blockIdx.x * 32 + pl;             // 4608 blocks * 32 == NPIX
    int b = p / HW, r = p - b * HW, y = r / Ww, x = r - y * Ww;

    int yy = y + c_oy[g] * shift, xx = x + c_ox[g] * shift;
    bool valid = ((unsigned)yy < Hh) && ((unsigned)xx < Ww);
    float sign = (g == 8) ? 1.f : -1.f;
    int sidx = valid ? (b * HW + yy * Ww + xx) : 0;

    float v[16];
#pragma unroll
    for (int j = 0; j < 4; j++) {
        float4 t = g_h4[br][j][sidx];
        if (!valid) t = make_float4(0.f, 0.f, 0.f, 0.f);
        v[4*j+0] = sign * t.x; v[4*j+1] = sign * t.y;
        v[4*j+2] = sign * t.z; v[4*j+3] = sign * t.w;
    }

    float o[16];
    // ---- o1 -> smem exchange
#pragma unroll
    for (int j = 0; j < 16; j++) o[j] = 0.f;
    {
        const float* Wg = W1s + g * 256;
#pragma unroll
        for (int c = 0; c < 16; c++) {
            float vc = v[c];
            const float4* w4 = (const float4*)(Wg + c * 16);
#pragma unroll
            for (int j = 0; j < 4; j++) {
                float4 w = w4[j];
                o[4*j+0] = fmaf(w.x, vc, o[4*j+0]);
                o[4*j+1] = fmaf(w.y, vc, o[4*j+1]);
                o[4*j+2] = fmaf(w.z, vc, o[4*j+2]);
                o[4*j+3] = fmaf(w.w, vc, o[4*j+3]);
            }
        }
    }
#pragma unroll
    for (int d = 0; d < 16; d++) o1s[(g * 16 + d) * XS + pl] = o[d];

    // ---- o3 -> smem exchange
#pragma unroll
    for (int j = 0; j < 16; j++) o[j] = 0.f;
    {
        const float* Wg = W3s + g * 256;
#pragma unroll
        for (int c = 0; c < 16; c++) {
            float vc = v[c];
            const float4* w4 = (const float4*)(Wg + c * 16);
#pragma unroll
            for (int j = 0; j < 4; j++) {
                float4 w = w4[j];
                o[4*j+0] = fmaf(w.x, vc, o[4*j+0]);
                o[4*j+1] = fmaf(w.y, vc, o[4*j+1]);
                o[4*j+2] = fmaf(w.z, vc, o[4*j+2]);
                o[4*j+3] = fmaf(w.w, vc, o[4*j+3]);
            }
        }
    }
#pragma unroll
    for (int d = 0; d < 16; d++) o3s[(g * 16 + d) * XS + pl] = o[d];

    // ---- o2 stays in regs
#pragma unroll
    for (int j = 0; j < 16; j++) o[j] = 0.f;
    {
        const float* Wg = W2s + g * 256;
#pragma unroll
        for (int c = 0; c < 16; c++) {
            float vc = v[c];
            const float4* w4 = (const float4*)(Wg + c * 16);
#pragma unroll
            for (int j = 0; j < 4; j++) {
                float4 w = w4[j];
                o[4*j+0] = fmaf(w.x, vc, o[4*j+0]);
                o[4*j+1] = fmaf(w.y, vc, o[4*j+1]);
                o[4*j+2] = fmaf(w.z, vc, o[4*j+2]);
                o[4*j+3] = fmaf(w.w, vc, o[4*j+3]);
            }
        }
    }
    __syncthreads();

    float sc = __ldg(scl + br);
    float l[9];
#pragma unroll
    for (int q = 0; q < 9; q++) {
        const float* oq = o1s + q * 16 * XS + pl;
        float s = 0.f;
#pragma unroll
        for (int d = 0; d < 16; d++)
            s = fmaf(o[d], oq[d * XS], s);
        l[q] = s * sc;
    }
    float m = l[0];
#pragma unroll
    for (int q = 1; q < 9; q++) m = fmaxf(m, l[q]);
    float ssum = 0.f;
#pragma unroll
    for (int q = 0; q < 9; q++) { l[q] = __expf(l[q] - m); ssum += l[q]; }
    float inv = 1.f / ssum;

    float outv[16];
#pragma unroll
    for (int j = 0; j < 16; j++) outv[j] = 0.f;
#pragma unroll
    for (int q = 0; q < 9; q++) {
        float a = l[q] * inv;
        const float* oq = o3s + q * 16 * XS + pl;
#pragma unroll
        for (int d = 0; d < 16; d++)
            outv[d] = fmaf(a, oq[d * XS], outv[d]);
    }
    // channel-major coalesced store
#pragma unroll
    for (int d = 0; d < 16; d++)
        g_mid[br * 144 + g * 16 + d][p] = outv[d];
}

// ---------------------------------------------------------------------------
// Kernel 3: final 1x1 conv (288 -> 128) + bias.
// 512 threads = 256 pixels x 2 output halves (64 ch each), acc in regs.
// mid is channel-major -> coalesced scalar loads.
// Weight smem: ws[i*WSTR + o] (transposed), init via coalesced float4 reads.
// ---------------------------------------------------------------------------
__global__ void __launch_bounds__(512) k_out(const float* __restrict__ ow,
                                             const float* __restrict__ ob,
                                             float* __restrict__ out) {
    extern __shared__ float ws[];              // [288][WSTR], 152064 B
    // ow is (OUTC, MIDC): row o has 288 floats = 72 float4, read coalesced.
    const float4* ow4 = (const float4*)ow;
    for (int t = threadIdx.x; t < OUTC * (MIDC / 4); t += 512) {
        int o = t / (MIDC / 4);
        int i4 = t - o * (MIDC / 4);
        float4 v = __ldg(ow4 + t);
        int i = i4 * 4;
        ws[(i + 0) * WSTR + o] = v.x;
        ws[(i + 1) * WSTR + o] = v.y;
        ws[(i + 2) * WSTR + o] = v.z;
        ws[(i + 3) * WSTR + o] = v.w;
    }
    __syncthreads();

    int half = threadIdx.x & 1;
    int pl = threadIdx.x >> 1;                 // 0..255
    int p = blockIdx.x * 256 + pl;             // 576 blocks * 256 == NPIX
    int b = p / HW, r = p - b * HW;

    float acc[64];
#pragma unroll
    for (int j = 0; j < 64; j++) acc[j] = __ldg(ob + half * 64 + j);

#pragma unroll 4
    for (int i = 0; i < MIDC; i++) {
        float mm = g_mid[i][p];
        const float4* w4 = (const float4*)(ws + i * WSTR + half * 64);
#pragma unroll
        for (int j = 0; j < 16; j++) {
            float4 w = w4[j];
            acc[4*j+0] = fmaf(w.x, mm, acc[4*j+0]);
            acc[4*j+1] = fmaf(w.y, mm, acc[4*j+1]);
            acc[4*j+2] = fmaf(w.z, mm, acc[4*j+2]);
            acc[4*j+3] = fmaf(w.w, mm, acc[4*j+3]);
        }
    }
    float* op = out + (size_t)b * OUTC * HW + r;
#pragma unroll
    for (int j = 0; j < 64; j++)
        op[(size_t)(half * 64 + j) * HW] = acc[j];
}

// ---------------------------------------------------------------------------
extern "C" void kernel_launch(void* const* d_in, const int* in_sizes, int n_in,
                              void* d_out, int out_size) {
    const float* cen   = (const float*)d_in[0];
    const float* in_w0 = (const float*)d_in[1];
    const float* in_b0 = (const float*)d_in[2];
    const float* in_w1 = (const float*)d_in[3];
    const float* in_b1 = (const float*)d_in[4];
    const float* w1_0  = (const float*)d_in[5];
    const float* w2_0  = (const float*)d_in[6];
    const float* w3_0  = (const float*)d_in[7];
    const float* w1_1  = (const float*)d_in[8];
    const float* w2_1  = (const float*)d_in[9];
    const float* w3_1  = (const float*)d_in[10];
    const float* scale = (const float*)d_in[11];
    const float* out_w = (const float*)d_in[12];
    const float* out_b = (const float*)d_in[13];
    float* out = (float*)d_out;

    const int attnSmem = (6912 + 2 * 144 * XS) * (int)sizeof(float);      // 65664 B
    const int outSmem  = MIDC * WSTR * (int)sizeof(float);                // 152064 B
    cudaFuncSetAttribute(k_attn, cudaFuncAttributeMaxDynamicSharedMemorySize, attnSmem);
    cudaFuncSetAttribute(k_out,  cudaFuncAttributeMaxDynamicSharedMemorySize, outSmem);

    k_proj1x1<<<NPIX / 256, 256>>>(cen, in_w0, in_b0);
    k_proj3x3<<<dim3(Ww / 64, Hh / 4, 4), 256>>>(cen, in_w1, in_b1);
    k_attn<<<NPIX / 32, 288, attnSmem>>>(w1_0, w2_0, w3_0, scale, 0, 1);
    k_attn<<<NPIX / 32, 288, attnSmem>>>(w1_1, w2_1, w3_1, scale, 1, 5);
    k_out<<<NPIX / 256, 512, outSmem>>>(out_w, out_b, out);
}

// round 9
// speedup vs baseline: 2.9652x; 1.4525x over previous
#include <cuda_runtime.h>
#include <cstdint>

#define Hh 192
#define Ww 192
#define HW 36864
#define NPIX 147456
#define INC 256
#define HID 16
#define MIDC 288
#define OUTC 128
#define XS 33            // exchange stride (floats) for o1s/o3s: conflict-free
#define KS 136           // k_out smem row stride in words (== 8 mod 32 -> conflict-free frags)

// Scratch (device globals: allocation-free per harness rules)
__device__ float4 g_h4[2][4][NPIX];      // (branch, ch-chunk, pixel) plane-major ~18.9 MB
__device__ float  g_midT[NPIX][MIDC];    // pixel-major (K-contiguous for MMA B) ~162 MB

// group -> spatial offset (unit steps; multiplied by shift). g==8 is center (+h).
__constant__ int c_oy[9] = {-1,-1,-1, 0, 1, 1, 1, 0, 0};
__constant__ int c_ox[9] = {-1, 0, 1, 1, 1, 0,-1,-1, 0};

__device__ __forceinline__ uint32_t f2tf32(float v) {
    uint32_t u;
    asm("cvt.rna.tf32.f32 %0, %1;" : "=r"(u) : "f"(v));
    return u;
}

// ---------------------------------------------------------------------------
// Kernel 1a: 1x1 input projection (branch 0): h0 = W0 * cen + b0
// ---------------------------------------------------------------------------
__global__ void __launch_bounds__(256) k_proj1x1(const float* __restrict__ cen,
                                                 const float* __restrict__ w0,
                                                 const float* __restrict__ b0) {
    __shared__ float ws[INC][HID];            // ws[c][o] = w0[o, c]
    for (int t = threadIdx.x; t < INC * HID; t += 256) {
        int c = t >> 4, o = t & 15;
        ws[c][o] = __ldg(w0 + o * INC + c);
    }
    __syncthreads();

    int p = blockIdx.x * 256 + threadIdx.x;   // 576 blocks * 256 == NPIX exactly
    int b = p / HW, r = p - b * HW;

    float acc[HID];
#pragma unroll
    for (int o = 0; o < HID; o++) acc[o] = __ldg(b0 + o);

    const float* cp = cen + (size_t)b * INC * HW + r;
#pragma unroll 4
    for (int c = 0; c < INC; c++) {
        float v = __ldg(cp + (size_t)c * HW);
        const float4* w4 = (const float4*)ws[c];
#pragma unroll
        for (int j = 0; j < 4; j++) {
            float4 w = w4[j];
            acc[4*j+0] = fmaf(w.x, v, acc[4*j+0]);
            acc[4*j+1] = fmaf(w.y, v, acc[4*j+1]);
            acc[4*j+2] = fmaf(w.z, v, acc[4*j+2]);
            acc[4*j+3] = fmaf(w.w, v, acc[4*j+3]);
        }
    }
#pragma unroll
    for (int j = 0; j < 4; j++)
        g_h4[0][j][p] = make_float4(acc[4*j], acc[4*j+1], acc[4*j+2], acc[4*j+3]);
}

// ---------------------------------------------------------------------------
// Kernel 1b: 3x3 SAME input projection (branch 1): h1 = conv3x3(cen, W1) + b1
// Block: 256 threads = 64x4 pixel tile. Channels staged in chunks of 16.
// ---------------------------------------------------------------------------
#define CH 16
__global__ void __launch_bounds__(256) k_proj3x3(const float* __restrict__ cen,
                                                 const float* __restrict__ w1,
                                                 const float* __restrict__ b1) {
    __shared__ float tile[CH][6][66];          // (4+2) x (64+2) halo tile per channel
    __shared__ float ws[CH][9][HID];           // ws[cc][tap][o]

    int tx = threadIdx.x & 63, ty = threadIdx.x >> 6;
    int x0 = blockIdx.x * 64, y0 = blockIdx.y * 4, b = blockIdx.z;

    float acc[HID];
#pragma unroll
    for (int o = 0; o < HID; o++) acc[o] = __ldg(b1 + o);

    for (int c0 = 0; c0 < INC; c0 += CH) {
        __syncthreads();  // protect smem from previous chunk's compute
        for (int t = threadIdx.x; t < CH * 6 * 66; t += 256) {
            int cc = t / 396; int rem = t - cc * 396;
            int rr = rem / 66; int col = rem - rr * 66;
            int y = y0 - 1 + rr, x = x0 - 1 + col;
            float v = 0.f;
            if ((unsigned)y < Hh && (unsigned)x < Ww)
                v = __ldg(cen + (size_t)(b * INC + c0 + cc) * HW + y * Ww + x);
            tile[cc][rr][col] = v;
        }
        for (int t = threadIdx.x; t < CH * 9 * HID; t += 256) {
            int cc = t / 144; int rem = t - cc * 144;
            int k9 = rem >> 4; int o = rem & 15;
            ws[cc][k9][o] = __ldg(w1 + (size_t)(o * INC + c0 + cc) * 9 + k9);
        }
        __syncthreads();

#pragma unroll 2
        for (int cc = 0; cc < CH; cc++) {
            float r[9];
#pragma unroll
            for (int dy = 0; dy < 3; dy++)
#pragma unroll
                for (int dx = 0; dx < 3; dx++)
                    r[dy*3+dx] = tile[cc][ty + dy][tx + dx];
#pragma unroll
            for (int k = 0; k < 9; k++) {
                const float4* w4 = (const float4*)ws[cc][k];
#pragma unroll
                for (int j = 0; j < 4; j++) {
                    float4 w = w4[j];
                    acc[4*j+0] = fmaf(w.x, r[k], acc[4*j+0]);
                    acc[4*j+1] = fmaf(w.y, r[k], acc[4*j+1]);
                    acc[4*j+2] = fmaf(w.z, r[k], acc[4*j+2]);
                    acc[4*j+3] = fmaf(w.w, r[k], acc[4*j+3]);
                }
            }
        }
    }

    int p = b * HW + (y0 + ty) * Ww + (x0 + tx);
#pragma unroll
    for (int j = 0; j < 4; j++)
        g_h4[1][j][p] = make_float4(acc[4*j], acc[4*j+1], acc[4*j+2], acc[4*j+3]);
}

// ---------------------------------------------------------------------------
// Kernel 2: per-pixel group attention for one branch.
// Block: 288 threads = 9 warps; warp = group g, lane = pixel.
// ---------------------------------------------------------------------------
__global__ void __launch_bounds__(288) k_attn(const float* __restrict__ w1,
                                              const float* __restrict__ w2,
                                              const float* __restrict__ w3,
                                              const float* __restrict__ scl,
                                              int br, int shift) {
    extern __shared__ float sm[];
    float* W1s = sm;                 // [9][16(c)][16(d)]
    float* W2s = sm + 2304;
    float* W3s = sm + 4608;
    float* o1s = sm + 6912;          // [144][XS]
    float* o3s = o1s + 144 * XS;

    for (int t = threadIdx.x; t < 2304; t += 288) {
        int g = t >> 8; int rem = t & 255; int c = rem >> 4; int d = rem & 15;
        int src = (g * 16 + d) * 16 + c;       // weights are (9, d, c)
        W1s[t] = __ldg(w1 + src);
        W2s[t] = __ldg(w2 + src);
        W3s[t] = __ldg(w3 + src);
    }
    __syncthreads();

    int g  = threadIdx.x >> 5;                 // warp id == group (0..8)
    int pl = threadIdx.x & 31;                 // lane == pixel within block
    int p  = blockIdx.x * 32 + pl;             // 4608 blocks * 32 == NPIX
    int b = p / HW, r = p - b * HW, y = r / Ww, x = r - y * Ww;

    int yy = y + c_oy[g] * shift, xx = x + c_ox[g] * shift;
    bool valid = ((unsigned)yy < Hh) && ((unsigned)xx < Ww);
    float sign = (g == 8) ? 1.f : -1.f;
    int sidx = valid ? (b * HW + yy * Ww + xx) : 0;

    float v[16];
#pragma unroll
    for (int j = 0; j < 4; j++) {
        float4 t = g_h4[br][j][sidx];
        if (!valid) t = make_float4(0.f, 0.f, 0.f, 0.f);
        v[4*j+0] = sign * t.x; v[4*j+1] = sign * t.y;
        v[4*j+2] = sign * t.z; v[4*j+3] = sign * t.w;
    }

    float o[16];
    // ---- o1 -> smem exchange
#pragma unroll
    for (int j = 0; j < 16; j++) o[j] = 0.f;
    {
        const float* Wg = W1s + g * 256;
#pragma unroll
        for (int c = 0; c < 16; c++) {
            float vc = v[c];
            const float4* w4 = (const float4*)(Wg + c * 16);
#pragma unroll
            for (int j = 0; j < 4; j++) {
                float4 w = w4[j];
                o[4*j+0] = fmaf(w.x, vc, o[4*j+0]);
                o[4*j+1] = fmaf(w.y, vc, o[4*j+1]);
                o[4*j+2] = fmaf(w.z, vc, o[4*j+2]);
                o[4*j+3] = fmaf(w.w, vc, o[4*j+3]);
            }
        }
    }
#pragma unroll
    for (int d = 0; d < 16; d++) o1s[(g * 16 + d) * XS + pl] = o[d];

    // ---- o3 -> smem exchange
#pragma unroll
    for (int j = 0; j < 16; j++) o[j] = 0.f;
    {
        const float* Wg = W3s + g * 256;
#pragma unroll
        for (int c = 0; c < 16; c++) {
            float vc = v[c];
            const float4* w4 = (const float4*)(Wg + c * 16);
#pragma unroll
            for (int j = 0; j < 4; j++) {
                float4 w = w4[j];
                o[4*j+0] = fmaf(w.x, vc, o[4*j+0]);
                o[4*j+1] = fmaf(w.y, vc, o[4*j+1]);
                o[4*j+2] = fmaf(w.z, vc, o[4*j+2]);
                o[4*j+3] = fmaf(w.w, vc, o[4*j+3]);
            }
        }
    }
#pragma unroll
    for (int d = 0; d < 16; d++) o3s[(g * 16 + d) * XS + pl] = o[d];

    // ---- o2 stays in regs
#pragma unroll
    for (int j = 0; j < 16; j++) o[j] = 0.f;
    {
        const float* Wg = W2s + g * 256;
#pragma unroll
        for (int c = 0; c < 16; c++) {
            float vc = v[c];
            const float4* w4 = (const float4*)(Wg + c * 16);
#pragma unroll
            for (int j = 0; j < 4; j++) {
                float4 w = w4[j];
                o[4*j+0] = fmaf(w.x, vc, o[4*j+0]);
                o[4*j+1] = fmaf(w.y, vc, o[4*j+1]);
                o[4*j+2] = fmaf(w.z, vc, o[4*j+2]);
                o[4*j+3] = fmaf(w.w, vc, o[4*j+3]);
            }
        }
    }
    __syncthreads();

    float sc = __ldg(scl + br);
    float l[9];
#pragma unroll
    for (int q = 0; q < 9; q++) {
        const float* oq = o1s + q * 16 * XS + pl;
        float s = 0.f;
#pragma unroll
        for (int d = 0; d < 16; d++)
            s = fmaf(o[d], oq[d * XS], s);
        l[q] = s * sc;
    }
    float m = l[0];
#pragma unroll
    for (int q = 1; q < 9; q++) m = fmaxf(m, l[q]);
    float ssum = 0.f;
#pragma unroll
    for (int q = 0; q < 9; q++) { l[q] = __expf(l[q] - m); ssum += l[q]; }
    float inv = 1.f / ssum;

    float outv[16];
#pragma unroll
    for (int j = 0; j < 16; j++) outv[j] = 0.f;
#pragma unroll
    for (int q = 0; q < 9; q++) {
        float a = l[q] * inv;
        const float* oq = o3s + q * 16 * XS + pl;
#pragma unroll
        for (int d = 0; d < 16; d++)
            outv[d] = fmaf(a, oq[d * XS], outv[d]);
    }
    // pixel-major store (K-contiguous for the MMA B operand)
    float4* mp = (float4*)(g_midT[p] + br * 144 + g * 16);
#pragma unroll
    for (int j = 0; j < 4; j++)
        mp[j] = make_float4(outv[4*j], outv[4*j+1], outv[4*j+2], outv[4*j+3]);
}

// ---------------------------------------------------------------------------
// Kernel 3 (mma.sync tf32): out[128ch, 128pix/block] = W[128,288] . midT^T
// 8 warps; warp tile = 64ch x 32pix (4 m-tiles x 4 n-tiles of m16n8k8).
// smem [k][m]/[k][n] with row stride KS=136 words (8 mod 32): conflict-free
// fragment loads (bank = 8c + r covers 0..31 exactly).
// ---------------------------------------------------------------------------
__global__ void __launch_bounds__(256) k_out_mma(const float* __restrict__ ow,
                                                 const float* __restrict__ ob,
                                                 float* __restrict__ out) {
    __shared__ uint32_t sA[32 * KS];   // [k][ch]  tf32 bits
    __shared__ uint32_t sB[32 * KS];   // [k][pix] tf32 bits

    int tid = threadIdx.x;
    int wid = tid >> 5, lane = tid & 31;
    int r = lane >> 2, c = lane & 3;
    int chbase = (wid & 1) * 64;
    int pixbase = (wid >> 1) * 32;
    int p0 = blockIdx.x * 128;                 // 1152 blocks; never straddles batch
    int b = p0 / HW, r0 = p0 - b * HW;

    float acc[4][4][4];
#pragma unroll
    for (int mt = 0; mt < 4; mt++)
#pragma unroll
        for (int nt = 0; nt < 4; nt++)
#pragma unroll
            for (int j = 0; j < 4; j++) acc[mt][nt][j] = 0.f;

    for (int ch = 0; ch < 9; ch++) {           // K chunks of 32
        __syncthreads();
#pragma unroll
        for (int t = tid; t < 1024; t += 256) {
            int row = t >> 3, f4 = t & 7;      // row: 0..127, f4: 0..7
            float4 wv = __ldg((const float4*)(ow + (size_t)row * MIDC + ch * 32 + f4 * 4));
            sA[(f4 * 4 + 0) * KS + row] = f2tf32(wv.x);
            sA[(f4 * 4 + 1) * KS + row] = f2tf32(wv.y);
            sA[(f4 * 4 + 2) * KS + row] = f2tf32(wv.z);
            sA[(f4 * 4 + 3) * KS + row] = f2tf32(wv.w);
            float4 mv = *(const float4*)(g_midT[p0 + row] + ch * 32 + f4 * 4);
            sB[(f4 * 4 + 0) * KS + row] = f2tf32(mv.x);
            sB[(f4 * 4 + 1) * KS + row] = f2tf32(mv.y);
            sB[(f4 * 4 + 2) * KS + row] = f2tf32(mv.z);
            sB[(f4 * 4 + 3) * KS + row] = f2tf32(mv.w);
        }
        __syncthreads();

#pragma unroll
        for (int ks = 0; ks < 4; ks++) {
            int k = ks * 8;
            uint32_t a[4][4];
#pragma unroll
            for (int mt = 0; mt < 4; mt++) {
                int chh = chbase + mt * 16 + r;
                a[mt][0] = sA[(k + c) * KS + chh];
                a[mt][1] = sA[(k + c) * KS + chh + 8];
                a[mt][2] = sA[(k + c + 4) * KS + chh];
                a[mt][3] = sA[(k + c + 4) * KS + chh + 8];
            }
            uint32_t bf[4][2];
#pragma unroll
            for (int nt = 0; nt < 4; nt++) {
                int px = pixbase + nt * 8 + r;
                bf[nt][0] = sB[(k + c) * KS + px];
                bf[nt][1] = sB[(k + c + 4) * KS + px];
            }
#pragma unroll
            for (int mt = 0; mt < 4; mt++)
#pragma unroll
                for (int nt = 0; nt < 4; nt++) {
                    asm volatile(
                        "mma.sync.aligned.m16n8k8.row.col.f32.tf32.tf32.f32 "
                        "{%0,%1,%2,%3}, {%4,%5,%6,%7}, {%8,%9}, {%0,%1,%2,%3};"
                        : "+f"(acc[mt][nt][0]), "+f"(acc[mt][nt][1]),
                          "+f"(acc[mt][nt][2]), "+f"(acc[mt][nt][3])
                        : "r"(a[mt][0]), "r"(a[mt][1]), "r"(a[mt][2]), "r"(a[mt][3]),
                          "r"(bf[nt][0]), "r"(bf[nt][1]));
                }
        }
    }

    // Epilogue: add bias, store. c0/c1 -> (ch0, pix 2c..2c+1); c2/c3 -> ch0+8.
#pragma unroll
    for (int mt = 0; mt < 4; mt++) {
        int ch0 = chbase + mt * 16 + r;
        float bias0 = __ldg(ob + ch0);
        float bias1 = __ldg(ob + ch0 + 8);
        float* row0 = out + ((size_t)b * OUTC + ch0) * HW + r0;
#pragma unroll
        for (int nt = 0; nt < 4; nt++) {
            int pix = pixbase + nt * 8 + 2 * c;
            float2 v0 = make_float2(acc[mt][nt][0] + bias0, acc[mt][nt][1] + bias0);
            float2 v1 = make_float2(acc[mt][nt][2] + bias1, acc[mt][nt][3] + bias1);
            *(float2*)(row0 + pix) = v0;
            *(float2*)(row0 + (size_t)8 * HW + pix) = v1;
        }
    }
}

// ---------------------------------------------------------------------------
extern "C" void kernel_launch(void* const* d_in, const int* in_sizes, int n_in,
                              void* d_out, int out_size) {
    const float* cen   = (const float*)d_in[0];
    const float* in_w0 = (const float*)d_in[1];
    const float* in_b0 = (const float*)d_in[2];
    const float* in_w1 = (const float*)d_in[3];
    const float* in_b1 = (const float*)d_in[4];
    const float* w1_0  = (const float*)d_in[5];
    const float* w2_0  = (const float*)d_in[6];
    const float* w3_0  = (const float*)d_in[7];
    const float* w1_1  = (const float*)d_in[8];
    const float* w2_1  = (const float*)d_in[9];
    const float* w3_1  = (const float*)d_in[10];
    const float* scale = (const float*)d_in[11];
    const float* out_w = (const float*)d_in[12];
    const float* out_b = (const float*)d_in[13];
    float* out = (float*)d_out;

    const int attnSmem = (6912 + 2 * 144 * XS) * (int)sizeof(float);      // 65664 B
    cudaFuncSetAttribute(k_attn, cudaFuncAttributeMaxDynamicSharedMemorySize, attnSmem);

    k_proj1x1<<<NPIX / 256, 256>>>(cen, in_w0, in_b0);
    k_proj3x3<<<dim3(Ww / 64, Hh / 4, 4), 256>>>(cen, in_w1, in_b1);
    k_attn<<<NPIX / 32, 288, attnSmem>>>(w1_0, w2_0, w3_0, scale, 0, 1);
    k_attn<<<NPIX / 32, 288, attnSmem>>>(w1_1, w2_1, w3_1, scale, 1, 5);
    k_out_mma<<<NPIX / 128, 256>>>(out_w, out_b, out);
}

// round 11
// speedup vs baseline: 3.4710x; 1.1706x over previous
#include <cuda_runtime.h>
#include <cstdint>

#define Hh 192
#define Ww 192
#define HW 36864
#define NPIX 147456
#define INC 256
#define HID 16
#define MIDC 288
#define OUTC 128
#define XS 33            // attn exchange stride: conflict-free
#define KS 136           // k_out smem row stride (words), ==8 mod 32
#define PLS 680          // proj3x3 tile plane stride (words), ==8 mod 32

// Scratch (device globals: allocation-free per harness rules)
__device__ float4 g_h4[2][4][NPIX];      // (branch, ch-chunk, pixel) plane-major ~18.9 MB
__device__ float  g_midT[NPIX][MIDC];    // pixel-major (K-contiguous for MMA B) ~162 MB

// group -> spatial offset (unit steps; multiplied by shift). g==8 is center (+h).
__constant__ int c_oy[9] = {-1,-1,-1, 0, 1, 1, 1, 0, 0};
__constant__ int c_ox[9] = {-1, 0, 1, 1, 1, 0,-1,-1, 0};

__device__ __forceinline__ uint32_t f2tf32(float v) {
    uint32_t u;
    asm("cvt.rna.tf32.f32 %0, %1;" : "=r"(u) : "f"(v));
    return u;
}
#define MMA_TF32(acc, a, b)                                                        \
    asm volatile("mma.sync.aligned.m16n8k8.row.col.f32.tf32.tf32.f32 "             \
                 "{%0,%1,%2,%3}, {%4,%5,%6,%7}, {%8,%9}, {%0,%1,%2,%3};"           \
                 : "+f"(acc[0]), "+f"(acc[1]), "+f"(acc[2]), "+f"(acc[3])          \
                 : "r"(a[0]), "r"(a[1]), "r"(a[2]), "r"(a[3]), "r"(b[0]), "r"(b[1]))

// ---------------------------------------------------------------------------
// Kernel 1a: 1x1 input projection (branch 0): h0 = W0 * cen + b0
// ---------------------------------------------------------------------------
__global__ void __launch_bounds__(256) k_proj1x1(const float* __restrict__ cen,
                                                 const float* __restrict__ w0,
                                                 const float* __restrict__ b0) {
    __shared__ float ws[INC][HID];            // ws[c][o] = w0[o, c]
    for (int t = threadIdx.x; t < INC * HID; t += 256) {
        int c = t >> 4, o = t & 15;
        ws[c][o] = __ldg(w0 + o * INC + c);
    }
    __syncthreads();

    int p = blockIdx.x * 256 + threadIdx.x;   // 576 blocks * 256 == NPIX exactly
    int b = p / HW, r = p - b * HW;

    float acc[HID];
#pragma unroll
    for (int o = 0; o < HID; o++) acc[o] = __ldg(b0 + o);

    const float* cp = cen + (size_t)b * INC * HW + r;
#pragma unroll 4
    for (int c = 0; c < INC; c++) {
        float v = __ldg(cp + (size_t)c * HW);
        const float4* w4 = (const float4*)ws[c];
#pragma unroll
        for (int j = 0; j < 4; j++) {
            float4 w = w4[j];
            acc[4*j+0] = fmaf(w.x, v, acc[4*j+0]);
            acc[4*j+1] = fmaf(w.y, v, acc[4*j+1]);
            acc[4*j+2] = fmaf(w.z, v, acc[4*j+2]);
            acc[4*j+3] = fmaf(w.w, v, acc[4*j+3]);
        }
    }
#pragma unroll
    for (int j = 0; j < 4; j++)
        g_h4[0][j][p] = make_float4(acc[4*j], acc[4*j+1], acc[4*j+2], acc[4*j+3]);
}

// ---------------------------------------------------------------------------
// Kernel 1b (mma.sync tf32): 3x3 SAME conv as 9 shifted GEMMs over a halo tile.
// Block: 256 thr / 8 warps; warp w = output row y0+w, 64 px, 16 out-ch.
// K = 2304 staged as 16 chunks of 16 ch; in-chunk 18 k8-steps (tap x 8-ch grp).
// smem: tile [16][10][66] plane stride PLS=680 (==8 mod 32 -> conflict-free),
//       A [144][16] stride 24 (==24 mod 32 -> conflict-free).
// ---------------------------------------------------------------------------
__global__ void __launch_bounds__(256) k_proj3x3_mma(const float* __restrict__ cen,
                                                     const float* __restrict__ w1,
                                                     const float* __restrict__ b1) {
    extern __shared__ float sm3[];
    float* tile = sm3;                  // 16 * PLS = 10880 floats
    uint32_t* sA = (uint32_t*)(sm3 + 16 * PLS);   // 144 * 24 = 3456

    int tid = threadIdx.x;
    int w = tid >> 5, lane = tid & 31;
    int r = lane >> 2, c = lane & 3;
    int x0 = blockIdx.x * 64, y0 = blockIdx.y * 8, b = blockIdx.z;

    float acc[8][4];
#pragma unroll
    for (int nt = 0; nt < 8; nt++)
#pragma unroll
        for (int j = 0; j < 4; j++) acc[nt][j] = 0.f;

    for (int s = 0; s < 16; s++) {             // 16 chunks of 16 channels
        int cc0 = s * 16;
        __syncthreads();
        // stage input halo tile: rows y0-1..y0+8, cols x0-1..x0+64
        for (int t = tid; t < 16 * 660; t += 256) {
            int cc = t / 660; int rem = t - cc * 660;
            int rr = rem / 66; int col = rem - rr * 66;
            int y = y0 - 1 + rr, x = x0 - 1 + col;
            float v = 0.f;
            if ((unsigned)y < Hh && (unsigned)x < Ww)
                v = __ldg(cen + (size_t)(b * INC + cc0 + cc) * HW + y * Ww + x);
            tile[cc * PLS + rr * 66 + col] = v;
        }
        // stage A (tf32 bits): kidx = tap*16 + cg*8 + kc
        for (int t = tid; t < 2304; t += 256) {
            int m = t & 15, kidx = t >> 4;
            int tap = kidx >> 4, cg = (kidx >> 3) & 1, kc = kidx & 7;
            sA[kidx * 24 + m] =
                f2tf32(__ldg(w1 + (size_t)m * (INC * 9) + (cc0 + cg * 8 + kc) * 9 + tap));
        }
        __syncthreads();

#pragma unroll 2
        for (int kstep = 0; kstep < 18; kstep++) {
            int tap = kstep >> 1, cg = kstep & 1;
            int dy = tap / 3, dx = tap - dy * 3;
            int k8 = kstep * 8;
            uint32_t a[4];
            a[0] = sA[(k8 + c) * 24 + r];
            a[1] = sA[(k8 + c) * 24 + r + 8];
            a[2] = sA[(k8 + c + 4) * 24 + r];
            a[3] = sA[(k8 + c + 4) * 24 + r + 8];
            const float* base0 = tile + (cg * 8 + c) * PLS + (w + dy) * 66 + r + dx;
            const float* base1 = base0 + 4 * PLS;
#pragma unroll
            for (int nt = 0; nt < 8; nt++) {
                uint32_t bf[2];
                bf[0] = f2tf32(base0[nt * 8]);
                bf[1] = f2tf32(base1[nt * 8]);
                MMA_TF32(acc[nt], a, bf);
            }
        }
    }

    // epilogue: bias, stage via smem (reuse tile region), coalesced g_h4 stores
    float bias0 = __ldg(b1 + r);
    float bias1 = __ldg(b1 + r + 8);
    __syncthreads();
    float* outs = tile + w * 1088;             // per-warp [16][68]
#pragma unroll
    for (int nt = 0; nt < 8; nt++) {
        int px = nt * 8 + 2 * c;
        outs[r * 68 + px]       = acc[nt][0] + bias0;
        outs[r * 68 + px + 1]   = acc[nt][1] + bias0;
        outs[(r + 8) * 68 + px]     = acc[nt][2] + bias1;
        outs[(r + 8) * 68 + px + 1] = acc[nt][3] + bias1;
    }
    __syncwarp();
    int prow = b * HW + (y0 + w) * Ww + x0;
#pragma unroll
    for (int i = 0; i < 8; i++) {
        int idx = i * 32 + lane;
        int px = idx & 63, j = idx >> 6;
        g_h4[1][j][prow + px] = make_float4(outs[(4*j+0) * 68 + px],
                                            outs[(4*j+1) * 68 + px],
                                            outs[(4*j+2) * 68 + px],
                                            outs[(4*j+3) * 68 + px]);
    }
}

// ---------------------------------------------------------------------------
// Kernel 2: per-pixel group attention for one branch.
// Block: 288 threads = 9 warps; warp = group g, lane = pixel.
// ---------------------------------------------------------------------------
__global__ void __launch_bounds__(288) k_attn(const float* __restrict__ w1,
                                              const float* __restrict__ w2,
                                              const float* __restrict__ w3,
                                              const float* __restrict__ scl,
                                              int br, int shift) {
    extern __shared__ float sm[];
    float* W1s = sm;                 // [9][16(c)][16(d)]
    float* W2s = sm + 2304;
    float* W3s = sm + 4608;
    float* o1s = sm + 6912;          // [144][XS]
    float* o3s = o1s + 144 * XS;

    for (int t = threadIdx.x; t < 2304; t += 288) {
        int g = t >> 8; int rem = t & 255; int c = rem >> 4; int d = rem & 15;
        int src = (g * 16 + d) * 16 + c;       // weights are (9, d, c)
        W1s[t] = __ldg(w1 + src);
        W2s[t] = __ldg(w2 + src);
        W3s[t] = __ldg(w3 + src);
    }
    __syncthreads();

    int g  = threadIdx.x >> 5;                 // warp id == group (0..8)
    int pl = threadIdx.x & 31;                 // lane == pixel within block
    int p  = blockIdx.x * 32 + pl;             // 4608 blocks * 32 == NPIX
    int b = p / HW, r = p - b * HW, y = r / Ww, x = r - y * Ww;

    int yy = y + c_oy[g] * shift, xx = x + c_ox[g] * shift;
    bool valid = ((unsigned)yy < Hh) && ((unsigned)xx < Ww);
    float sign = (g == 8) ? 1.f : -1.f;
    int sidx = valid ? (b * HW + yy * Ww + xx) : 0;

    float v[16];
#pragma unroll
    for (int j = 0; j < 4; j++) {
        float4 t = g_h4[br][j][sidx];
        if (!valid) t = make_float4(0.f, 0.f, 0.f, 0.f);
        v[4*j+0] = sign * t.x; v[4*j+1] = sign * t.y;
        v[4*j+2] = sign * t.z; v[4*j+3] = sign * t.w;
    }

    float o[16];
    // ---- o1 -> smem exchange
#pragma unroll
    for (int j = 0; j < 16; j++) o[j] = 0.f;
    {
        const float* Wg = W1s + g * 256;
#pragma unroll
        for (int c = 0; c < 16; c++) {
            float vc = v[c];
            const float4* w4 = (const float4*)(Wg + c * 16);
#pragma unroll
            for (int j = 0; j < 4; j++) {
                float4 w = w4[j];
                o[4*j+0] = fmaf(w.x, vc, o[4*j+0]);
                o[4*j+1] = fmaf(w.y, vc, o[4*j+1]);
                o[4*j+2] = fmaf(w.z, vc, o[4*j+2]);
                o[4*j+3] = fmaf(w.w, vc, o[4*j+3]);
            }
        }
    }
#pragma unroll
    for (int d = 0; d < 16; d++) o1s[(g * 16 + d) * XS + pl] = o[d];

    // ---- o3 -> smem exchange
#pragma unroll
    for (int j = 0; j < 16; j++) o[j] = 0.f;
    {
        const float* Wg = W3s + g * 256;
#pragma unroll
        for (int c = 0; c < 16; c++) {
            float vc = v[c];
            const float4* w4 = (const float4*)(Wg + c * 16);
#pragma unroll
            for (int j = 0; j < 4; j++) {
                float4 w = w4[j];
                o[4*j+0] = fmaf(w.x, vc, o[4*j+0]);
                o[4*j+1] = fmaf(w.y, vc, o[4*j+1]);
                o[4*j+2] = fmaf(w.z, vc, o[4*j+2]);
                o[4*j+3] = fmaf(w.w, vc, o[4*j+3]);
            }
        }
    }
#pragma unroll
    for (int d = 0; d < 16; d++) o3s[(g * 16 + d) * XS + pl] = o[d];

    // ---- o2 stays in regs
#pragma unroll
    for (int j = 0; j < 16; j++) o[j] = 0.f;
    {
        const float* Wg = W2s + g * 256;
#pragma unroll
        for (int c = 0; c < 16; c++) {
            float vc = v[c];
            const float4* w4 = (const float4*)(Wg + c * 16);
#pragma unroll
            for (int j = 0; j < 4; j++) {
                float4 w = w4[j];
                o[4*j+0] = fmaf(w.x, vc, o[4*j+0]);
                o[4*j+1] = fmaf(w.y, vc, o[4*j+1]);
                o[4*j+2] = fmaf(w.z, vc, o[4*j+2]);
                o[4*j+3] = fmaf(w.w, vc, o[4*j+3]);
            }
        }
    }
    __syncthreads();

    float sc = __ldg(scl + br);
    float l[9];
#pragma unroll
    for (int q = 0; q < 9; q++) {
        const float* oq = o1s + q * 16 * XS + pl;
        float s = 0.f;
#pragma unroll
        for (int d = 0; d < 16; d++)
            s = fmaf(o[d], oq[d * XS], s);
        l[q] = s * sc;
    }
    float m = l[0];
#pragma unroll
    for (int q = 1; q < 9; q++) m = fmaxf(m, l[q]);
    float ssum = 0.f;
#pragma unroll
    for (int q = 0; q < 9; q++) { l[q] = __expf(l[q] - m); ssum += l[q]; }
    float inv = 1.f / ssum;

    float outv[16];
#pragma unroll
    for (int j = 0; j < 16; j++) outv[j] = 0.f;
#pragma unroll
    for (int q = 0; q < 9; q++) {
        float a = l[q] * inv;
        const float* oq = o3s + q * 16 * XS + pl;
#pragma unroll
        for (int d = 0; d < 16; d++)
            outv[d] = fmaf(a, oq[d * XS], outv[d]);
    }
    // pixel-major store (K-contiguous for the MMA B operand)
    float4* mp = (float4*)(g_midT[p] + br * 144 + g * 16);
#pragma unroll
    for (int j = 0; j < 4; j++)
        mp[j] = make_float4(outv[4*j], outv[4*j+1], outv[4*j+2], outv[4*j+3]);
}

// ---------------------------------------------------------------------------
// Kernel 3 (mma.sync tf32): out[128ch, 128pix/block] = W[128,288] . midT^T
// ---------------------------------------------------------------------------
__global__ void __launch_bounds__(256) k_out_mma(const float* __restrict__ ow,
                                                 const float* __restrict__ ob,
                                                 float* __restrict__ out) {
    __shared__ uint32_t sA[32 * KS];   // [k][ch]  tf32 bits
    __shared__ uint32_t sB[32 * KS];   // [k][pix] tf32 bits

    int tid = threadIdx.x;
    int wid = tid >> 5, lane = tid & 31;
    int r = lane >> 2, c = lane & 3;
    int chbase = (wid & 1) * 64;
    int pixbase = (wid >> 1) * 32;
    int p0 = blockIdx.x * 128;                 // 1152 blocks; never straddles batch
    int b = p0 / HW, r0 = p0 - b * HW;

    float acc[4][4][4];
#pragma unroll
    for (int mt = 0; mt < 4; mt++)
#pragma unroll
        for (int nt = 0; nt < 4; nt++)
#pragma unroll
            for (int j = 0; j < 4; j++) acc[mt][nt][j] = 0.f;

    for (int ch = 0; ch < 9; ch++) {           // K chunks of 32
        __syncthreads();
#pragma unroll
        for (int t = tid; t < 1024; t += 256) {
            int row = t >> 3, f4 = t & 7;      // row: 0..127, f4: 0..7
            float4 wv = __ldg((const float4*)(ow + (size_t)row * MIDC + ch * 32 + f4 * 4));
            sA[(f4 * 4 + 0) * KS + row] = f2tf32(wv.x);
            sA[(f4 * 4 + 1) * KS + row] = f2tf32(wv.y);
            sA[(f4 * 4 + 2) * KS + row] = f2tf32(wv.z);
            sA[(f4 * 4 + 3) * KS + row] = f2tf32(wv.w);
            float4 mv = *(const float4*)(g_midT[p0 + row] + ch * 32 + f4 * 4);
            sB[(f4 * 4 + 0) * KS + row] = f2tf32(mv.x);
            sB[(f4 * 4 + 1) * KS + row] = f2tf32(mv.y);
            sB[(f4 * 4 + 2) * KS + row] = f2tf32(mv.z);
            sB[(f4 * 4 + 3) * KS + row] = f2tf32(mv.w);
        }
        __syncthreads();

#pragma unroll
        for (int ks = 0; ks < 4; ks++) {
            int k = ks * 8;
            uint32_t a[4][4];
#pragma unroll
            for (int mt = 0; mt < 4; mt++) {
                int chh = chbase + mt * 16 + r;
                a[mt][0] = sA[(k + c) * KS + chh];
                a[mt][1] = sA[(k + c) * KS + chh + 8];
                a[mt][2] = sA[(k + c + 4) * KS + chh];
                a[mt][3] = sA[(k + c + 4) * KS + chh + 8];
            }
            uint32_t bf[4][2];
#pragma unroll
            for (int nt = 0; nt < 4; nt++) {
                int px = pixbase + nt * 8 + r;
                bf[nt][0] = sB[(k + c) * KS + px];
                bf[nt][1] = sB[(k + c + 4) * KS + px];
            }
#pragma unroll
            for (int mt = 0; mt < 4; mt++)
#pragma unroll
                for (int nt = 0; nt < 4; nt++)
                    MMA_TF32(acc[mt][nt], a[mt], bf[nt]);
        }
    }

    // Epilogue: add bias, store. c0/c1 -> (ch0, pix 2c..2c+1); c2/c3 -> ch0+8.
#pragma unroll
    for (int mt = 0; mt < 4; mt++) {
        int ch0 = chbase + mt * 16 + r;
        float bias0 = __ldg(ob + ch0);
        float bias1 = __ldg(ob + ch0 + 8);
        float* row0 = out + ((size_t)b * OUTC + ch0) * HW + r0;
#pragma unroll
        for (int nt = 0; nt < 4; nt++) {
            int pix = pixbase + nt * 8 + 2 * c;
            float2 v0 = make_float2(acc[mt][nt][0] + bias0, acc[mt][nt][1] + bias0);
            float2 v1 = make_float2(acc[mt][nt][2] + bias1, acc[mt][nt][3] + bias1);
            *(float2*)(row0 + pix) = v0;
            *(float2*)(row0 + (size_t)8 * HW + pix) = v1;
        }
    }
}

// ---------------------------------------------------------------------------
extern "C" void kernel_launch(void* const* d_in, const int* in_sizes, int n_in,
                              void* d_out, int out_size) {
    const float* cen   = (const float*)d_in[0];
    const float* in_w0 = (const float*)d_in[1];
    const float* in_b0 = (const float*)d_in[2];
    const float* in_w1 = (const float*)d_in[3];
    const float* in_b1 = (const float*)d_in[4];
    const float* w1_0  = (const float*)d_in[5];
    const float* w2_0  = (const float*)d_in[6];
    const float* w3_0  = (const float*)d_in[7];
    const float* w1_1  = (const float*)d_in[8];
    const float* w2_1  = (const float*)d_in[9];
    const float* w3_1  = (const float*)d_in[10];
    const float* scale = (const float*)d_in[11];
    const float* out_w = (const float*)d_in[12];
    const float* out_b = (const float*)d_in[13];
    float* out = (float*)d_out;

    const int attnSmem = (6912 + 2 * 144 * XS) * (int)sizeof(float);      // 65664 B
    const int p3Smem   = (16 * PLS + 3456) * (int)sizeof(float);          // 57344 B
    cudaFuncSetAttribute(k_attn, cudaFuncAttributeMaxDynamicSharedMemorySize, attnSmem);
    cudaFuncSetAttribute(k_proj3x3_mma, cudaFuncAttributeMaxDynamicSharedMemorySize, p3Smem);

    k_proj1x1<<<NPIX / 256, 256>>>(cen, in_w0, in_b0);
    k_proj3x3_mma<<<dim3(3, 24, 4), 256, p3Smem>>>(cen, in_w1, in_b1);
    k_attn<<<NPIX / 32, 288, attnSmem>>>(w1_0, w2_0, w3_0, scale, 0, 1);
    k_attn<<<NPIX / 32, 288, attnSmem>>>(w1_1, w2_1, w3_1, scale, 1, 5);
    k_out_mma<<<NPIX / 128, 256>>>(out_w, out_b, out);
}